// round 16
// baseline (speedup 1.0000x reference)
#include <cuda_runtime.h>
#include <cuda_bf16.h>
#include <cstdint>
#include <math.h>

#define NE 100000
#define NR 400
#define DI 200
#define DO 400
#define NEDGE 600000
#define HALFE 300000
#define NB 1024
#define NGROUP 800
#define BN_EPS 1e-5f

#define KP 448
#define EN 448
#define EK 208

typedef unsigned long long u64;

// ---------------- device scratch ----------------
__device__ __nv_bfloat16 g_Mbh[(size_t)(NGROUP + 1) * EN * EK];
__device__ __nv_bfloat16 g_Mbl[(size_t)(NGROUP + 1) * EN * EK];
__device__ __nv_bfloat16 g_Wth[(size_t)3 * 448 * EK];
__device__ __nv_bfloat16 g_Wtl[(size_t)3 * 448 * EK];
__device__ float g_x[(size_t)NE * DO];
__device__ float g_stats[2 * DO];
__device__ float g_scale[DO];
__device__ float g_shift[DO];
__device__ float g_r[NR * DO];
__device__ __nv_bfloat16 g_obj_hi[NB * KP];
__device__ __nv_bfloat16 g_obj_lo[NB * KP];
__device__ __nv_bfloat16 g_emb_hi[(size_t)NE * KP];
__device__ __nv_bfloat16 g_emb_lo[(size_t)NE * KP];
__device__ int   g_hist[NGROUP];
__device__ int   g_off[NGROUP + 1];
__device__ int   g_pos[NGROUP];
__device__ int   g_eidx[NEDGE];

// ---------------- helpers ----------------
__device__ __forceinline__ void red4(float* p, float a, float b, float c, float d) {
    asm volatile("red.global.add.v4.f32 [%0], {%1,%2,%3,%4};"
                 :: "l"(p), "f"(a), "f"(b), "f"(c), "f"(d) : "memory");
}
__device__ __forceinline__ uint32_t smem_u32(const void* p) {
    uint32_t a;
    asm("{ .reg .u64 t; cvta.to.shared.u64 t, %1; cvt.u32.u64 %0, t; }" : "=r"(a) : "l"(p));
    return a;
}
__device__ __forceinline__ void ldsm_x4(uint32_t* r, uint32_t a) {
    asm volatile("ldmatrix.sync.aligned.m8n8.x4.shared.b16 {%0,%1,%2,%3}, [%4];"
                 : "=r"(r[0]), "=r"(r[1]), "=r"(r[2]), "=r"(r[3]) : "r"(a));
}
__device__ __forceinline__ void ldsm_x2(uint32_t* r, uint32_t a) {
    asm volatile("ldmatrix.sync.aligned.m8n8.x2.shared.b16 {%0,%1}, [%2];"
                 : "=r"(r[0]), "=r"(r[1]) : "r"(a));
}
__device__ __forceinline__ void mma16816(float* d, const uint32_t* a, const uint32_t* b) {
    asm volatile(
        "mma.sync.aligned.m16n8k16.row.col.f32.bf16.bf16.f32 "
        "{%0,%1,%2,%3}, {%4,%5,%6,%7}, {%8,%9}, {%0,%1,%2,%3};"
        : "+f"(d[0]), "+f"(d[1]), "+f"(d[2]), "+f"(d[3])
        : "r"(a[0]), "r"(a[1]), "r"(a[2]), "r"(a[3]), "r"(b[0]), "r"(b[1]));
}
__device__ __forceinline__ ushort bf16h(float v) {
    return __bfloat16_as_ushort(__float2bfloat16(v));
}
__device__ __forceinline__ ushort bf16l(float v) {
    __nv_bfloat16 h = __float2bfloat16(v);
    return __bfloat16_as_ushort(__float2bfloat16(v - __bfloat162float(h)));
}

// ---------------- zero small scratch ----------------
__global__ void k_zero() {
    int gid = blockIdx.x * blockDim.x + threadIdx.x;
    if (gid < NGROUP) g_hist[gid] = 0;
    if (gid < 2 * DO) g_stats[gid] = 0.f;
}

// ---------------- edge grouping: smem-aggregated hist ----------------
#define HB 148
__global__ void __launch_bounds__(1024) k_hist(const int* __restrict__ et) {
    __shared__ int sh[NGROUP];
    for (int i = threadIdx.x; i < NGROUP; i += 1024) sh[i] = 0;
    __syncthreads();
    int chunk = (NEDGE + HB - 1) / HB;
    int e0 = blockIdx.x * chunk;
    int e1 = min(e0 + chunk, NEDGE);
    for (int e = e0 + threadIdx.x; e < e1; e += 1024)
        atomicAdd(&sh[et[e] + (e < HALFE ? 0 : 400)], 1);
    __syncthreads();
    for (int i = threadIdx.x; i < NGROUP; i += 1024)
        if (sh[i]) atomicAdd(&g_hist[i], sh[i]);
}

__global__ void k_scan() {
    __shared__ int s[NGROUP];
    int i = threadIdx.x;
    if (i < NGROUP) s[i] = g_hist[i];
    __syncthreads();
    for (int d = 1; d < NGROUP; d <<= 1) {
        int v = 0;
        if (i < NGROUP && i >= d) v = s[i - d];
        __syncthreads();
        if (i < NGROUP && i >= d) s[i] += v;
        __syncthreads();
    }
    if (i < NGROUP) {
        int excl = s[i] - g_hist[i];
        g_off[i] = excl;
        g_pos[i] = excl;
        if (i == NGROUP - 1) g_off[NGROUP] = s[i];
    }
}

// ---------------- smem-aggregated scatter ----------------
__global__ void __launch_bounds__(1024) k_scatter(const int* __restrict__ et) {
    __shared__ int cnt[NGROUP];
    __shared__ int wr[NGROUP];
    for (int i = threadIdx.x; i < NGROUP; i += 1024) cnt[i] = 0;
    __syncthreads();
    int chunk = (NEDGE + HB - 1) / HB;
    int e0 = blockIdx.x * chunk;
    int e1 = min(e0 + chunk, NEDGE);
    for (int e = e0 + threadIdx.x; e < e1; e += 1024)
        atomicAdd(&cnt[et[e] + (e < HALFE ? 0 : 400)], 1);
    __syncthreads();
    for (int i = threadIdx.x; i < NGROUP; i += 1024)
        wr[i] = cnt[i] ? atomicAdd(&g_pos[i], cnt[i]) : 0;
    __syncthreads();
    for (int e = e0 + threadIdx.x; e < e1; e += 1024) {
        int g = et[e] + (e < HALFE ? 0 : 400);
        int p = atomicAdd(&wr[g], 1);
        g_eidx[p] = e;
    }
}

// ---------------- W^T bf16 split (once) ----------------
__global__ void k_splitW(const float* __restrict__ in_w, const float* __restrict__ out_w,
                         const float* __restrict__ loop_w) {
    int widx = blockIdx.y, o = blockIdx.x;
    const float* W = widx == 0 ? in_w : (widx == 1 ? out_w : loop_w);
    for (int j = threadIdx.x; j < EK; j += 256) {
        float v = (j < DI && o < DO) ? W[(size_t)j * DO + o] : 0.f;
        size_t off = ((size_t)widx * 448 + o) * EK + j;
        g_Wth[off] = __float2bfloat16(v);
        __nv_bfloat16 h = __float2bfloat16(v);
        g_Wtl[off] = __float2bfloat16(v - __bfloat162float(h));
    }
}

// ---------------- M^T = W^T @ C_b^T via mma.sync ----------------
#define MB 48
__global__ void __launch_bounds__(256) k_M_mma(
    const float* __restrict__ rel_emb, const float* __restrict__ loop_rel) {
    __shared__ ushort s_b[4][472];
    __shared__ char sA[2][64 * MB];
    __shared__ char sB[2][208 * MB];

    int m = blockIdx.y, strip = blockIdx.x;
    int widx = m < 400 ? 0 : (m < 800 ? 1 : 2);
    const float* bsrc = (m < 800) ? rel_emb + (size_t)(m % 400) * DI : loop_rel;
    int tid = threadIdx.x;

    for (int s = tid; s < 464; s += 256) {
        float v0 = bsrc[s % DI];
        float v1 = bsrc[(s + 1) % DI];
        s_b[0][s] = bf16h(v0);
        s_b[2][s] = bf16l(v0);
        s_b[1][s] = bf16h(v1);
        s_b[3][s] = bf16l(v1);
    }

    int wid = tid >> 5, lane = tid & 31;
    int wm = wid >> 1, wn = wid & 1;
    int gq = lane >> 2, tg = lane & 3;
    int mat = lane >> 3, r = lane & 7;
    uint32_t aoff = (uint32_t)(((mat & 1) * 8 + r) * MB + (mat >> 1) * 16);
    uint32_t boff = (uint32_t)(r * MB + ((lane >> 3) & 1) * 16);
    uint32_t baseA0 = smem_u32(sA[0]), baseA1 = smem_u32(sA[1]);
    uint32_t baseB0 = smem_u32(sB[0]), baseB1 = smem_u32(sB[1]);

    float acc[13][4] = {};

    for (int kc = 0; kc < 13; kc++) {
        __syncthreads();
        {
            int idx = tid;
            int p = idx >> 7, rem = idx & 127;
            int row = rem >> 1, half = rem & 1;
            const __nv_bfloat16* gW = p ? g_Wtl : g_Wth;
            size_t goff = ((size_t)widx * 448 + strip * 64 + row) * EK + kc * 16 + half * 8;
            *(uint4*)(sA[p] + row * MB + half * 16) = *(const uint4*)&gW[goff];
        }
        for (int idx = tid; idx < 416; idx += 256) {
            int p = (idx >= 208) ? 1 : 0;
            int t = idx - p * 208;
            int bi = t + kc * 16;
            int par = bi & 1;
            const uint32_t* sp = (const uint32_t*)&s_b[p * 2 + par][bi - par];
            uint32_t w0 = sp[0], w1 = sp[1], w2 = sp[2], w3 = sp[3];
            uint32_t w4 = sp[4], w5 = sp[5], w6 = sp[6], w7 = sp[7];
            *(uint4*)(sB[p] + t * MB) = make_uint4(w0, w1, w2, w3);
            *(uint4*)(sB[p] + t * MB + 16) = make_uint4(w4, w5, w6, w7);
        }
        __syncthreads();
        uint32_t ah[4], al[4];
        uint32_t ab = (uint32_t)((wm * 16) * MB) + aoff;
        ldsm_x4(ah, baseA0 + ab);
        ldsm_x4(al, baseA1 + ab);
#pragma unroll
        for (int nt = 0; nt < 13; nt++) {
            uint32_t bh2[2], bl2[2];
            uint32_t bb = (uint32_t)((wn * 104 + nt * 8) * MB) + boff;
            ldsm_x2(bh2, baseB0 + bb);
            ldsm_x2(bl2, baseB1 + bb);
            mma16816(acc[nt], ah, bh2);
            mma16816(acc[nt], ah, bl2);
            mma16816(acc[nt], al, bh2);
        }
    }

    const float S = 1.f / 3.f;
    int o0 = strip * 64 + wm * 16;
#pragma unroll
    for (int nt = 0; nt < 13; nt++) {
        int t = wn * 104 + nt * 8 + tg * 2;
#pragma unroll
        for (int rr = 0; rr < 2; rr++) {
            int o = o0 + gq + rr * 8;
            int ml = o & 15;
            int pm = ((ml & 2) << 2) | ((ml & 12) >> 1) | (ml & 1);
            int operm = (o & ~15) | pm;
            float v0 = acc[nt][rr * 2 + 0] * S, v1 = acc[nt][rr * 2 + 1] * S;
            uint32_t hp = (uint32_t)bf16h(v0) | ((uint32_t)bf16h(v1) << 16);
            uint32_t lp = (uint32_t)bf16l(v0) | ((uint32_t)bf16l(v1) << 16);
            size_t off = ((size_t)m * EN + operm) * EK + t;
            *(uint32_t*)&g_Mbh[off] = hp;
            *(uint32_t*)&g_Mbl[off] = lp;
        }
    }
}

// ---------------- edge messages: resident-B quarters, 512 threads, n-split warps ----------------
#define ET2 128
#define XSTR 432
#define EA_BYTES (ET2 * XSTR)
#define EB_BYTES (112 * XSTR)
#define EDGE_SMEM2 (2 * EA_BYTES + 2 * EB_BYTES)
#define ETH 512

template <int NTQ>
__device__ __forceinline__ void edge_body(
    int g, int q, const float* __restrict__ ent_emb, const int* __restrict__ src,
    const int* __restrict__ dst, const float* __restrict__ nrm,
    int* s_src, int* s_dst, float* s_nrm) {
    extern __shared__ char sm[];
    uint32_t sbase = smem_u32(sm);
    const uint32_t A_HI = 0, A_LO = EA_BYTES, B_HI = 2 * EA_BYTES,
                   B_LO = 2 * EA_BYTES + EB_BYTES;

    int base = g_off[g];
    int ng = g_off[g + 1] - base;
    if (ng == 0) return;
    const int ROWS = NTQ * 8;
    const int NPAIR = NTQ / 2;
    int tid = threadIdx.x, wid = tid >> 5, lane = tid & 31;
    int wm = wid & 7, wh = wid >> 3;             // row-tile, n-half
    int p0 = wh ? (NPAIR + 1) / 2 : 0;
    int p1 = wh ? NPAIR : (NPAIR + 1) / 2;
    int ntl0 = 2 * p0, ntl1 = 2 * p1;            // absolute n-tile range
    int gq = lane >> 2, tg = lane & 3;
    int mat = lane >> 3, r = lane & 7;
    uint32_t aoff = (uint32_t)(((mat & 1) * 8 + r) * XSTR + (mat >> 1) * 16);
    uint32_t boff = (uint32_t)(r * XSTR + ((lane >> 3) & 1) * 16);
    const __nv_bfloat16* Bh = g_Mbh + ((size_t)g * EN + q * 112) * EK;
    const __nv_bfloat16* Bl = g_Mbl + ((size_t)g * EN + q * 112) * EK;

    for (int idx = tid; idx < ROWS * 26 * 2; idx += ETH) {
        int p = (idx >= ROWS * 26) ? 1 : 0;
        int rem = idx - p * ROWS * 26;
        int row = rem / 26, seg = rem - row * 26;
        const __nv_bfloat16* gB = p ? Bl : Bh;
        uint32_t d = (p ? B_LO : B_HI) + row * XSTR + seg * 16;
        *(uint4*)(sm + d) = *(const uint4*)&gB[(size_t)row * EK + seg * 8];
    }

    for (int t0 = 0; t0 < ng; t0 += ET2) {
        int cnt = min(ET2, ng - t0);
        __syncthreads();
        if (tid < ET2) {
            if (tid < cnt) {
                int e = g_eidx[base + t0 + tid];
                s_src[tid] = src[e];
                s_dst[tid] = dst[e];
                s_nrm[tid] = nrm[e];
            } else {
                s_src[tid] = 0;
                s_dst[tid] = 0;
                s_nrm[tid] = 0.f;
            }
        }
        __syncthreads();
        for (int idx = tid; idx < ET2 * 26; idx += ETH) {
            int row = idx / 26, seg = idx - row * 26;
            uint32_t hi4[4] = {0, 0, 0, 0}, lo4[4] = {0, 0, 0, 0};
            if (seg < 25) {
                const float* p = &ent_emb[(size_t)s_src[row] * DI + seg * 8];
                float nv = s_nrm[row];
#pragma unroll
                for (int qd = 0; qd < 4; qd++) {
                    float v0 = p[qd * 2] * nv, v1 = p[qd * 2 + 1] * nv;
                    hi4[qd] = (uint32_t)bf16h(v0) | ((uint32_t)bf16h(v1) << 16);
                    lo4[qd] = (uint32_t)bf16l(v0) | ((uint32_t)bf16l(v1) << 16);
                }
            }
            uint32_t so = (uint32_t)(row * XSTR + seg * 16);
            *(uint4*)(sm + A_HI + so) = make_uint4(hi4[0], hi4[1], hi4[2], hi4[3]);
            *(uint4*)(sm + A_LO + so) = make_uint4(lo4[0], lo4[1], lo4[2], lo4[3]);
        }
        __syncthreads();

        float acc[8][4];   // up to 8 n-tiles per warp
#pragma unroll
        for (int nt = 0; nt < 8; nt++)
#pragma unroll
            for (int qd = 0; qd < 4; qd++) acc[nt][qd] = 0.f;

        for (int kc = 0; kc < 13; kc++) {
            uint32_t ah[4], al[4];
            uint32_t ab = (uint32_t)((wm * 16) * XSTR + kc * 32) + aoff;
            ldsm_x4(ah, sbase + A_HI + ab);
            ldsm_x4(al, sbase + A_LO + ab);
#pragma unroll 8
            for (int ntl = ntl0; ntl < ntl1; ntl++) {
                uint32_t bh2[2], bl2[2];
                uint32_t bb = (uint32_t)((ntl * 8) * XSTR + kc * 32) + boff;
                ldsm_x2(bh2, sbase + B_HI + bb);
                ldsm_x2(bl2, sbase + B_LO + bb);
                float* a = acc[ntl - ntl0];
                mma16816(a, ah, bh2);
                mma16816(a, ah, bl2);
                mma16816(a, al, bh2);
            }
        }

        int er0 = wm * 16 + gq;
        int er1 = er0 + 8;
        for (int pt = p0; pt < p1; pt++) {
            int c = q * 112 + pt * 16 + tg * 4;
            float* a0 = acc[2 * (pt - p0)];
            float* a1 = acc[2 * (pt - p0) + 1];
            if (er0 < cnt)
                red4(&g_x[(size_t)s_dst[er0] * DO + c], a0[0], a0[1], a1[0], a1[1]);
            if (er1 < cnt)
                red4(&g_x[(size_t)s_dst[er1] * DO + c], a0[2], a0[3], a1[2], a1[3]);
        }
    }
}

__global__ void __launch_bounds__(ETH) k_edge_mma(
    const float* __restrict__ ent_emb, const int* __restrict__ src,
    const int* __restrict__ dst, const float* __restrict__ nrm) {
    __shared__ int s_src[ET2];
    __shared__ int s_dst[ET2];
    __shared__ float s_nrm[ET2];
    int gq4 = blockIdx.y;
    int g = gq4 >> 2, q = gq4 & 3;
    if (q == 3)
        edge_body<8>(g, q, ent_emb, src, dst, nrm, s_src, s_dst, s_nrm);
    else
        edge_body<14>(g, q, ent_emb, src, dst, nrm, s_src, s_dst, s_nrm);
}

// ---------------- self-loop (runs FIRST): x = loop + bias ----------------
#define ASTR 432
#define BSTR 48
#define LA_BYTES (64 * ASTR)
#define LB_BYTES (EN * BSTR)
#define LOOP_SMEM (2 * LA_BYTES + 2 * LB_BYTES)

__global__ void __launch_bounds__(256) k_loopx_mma(
    const float* __restrict__ ent_emb, const float* __restrict__ bias_w) {
    extern __shared__ char sm[];
    uint32_t sbase = smem_u32(sm);
    const uint32_t A_HI = 0, A_LO = LA_BYTES, B_HI = 2 * LA_BYTES, B_LO = 2 * LA_BYTES + LB_BYTES;

    int tid = threadIdx.x, wid = tid >> 5, lane = tid & 31;
    int wm = wid >> 2, wn = wid & 3;
    int gq = lane >> 2, tg = lane & 3;
    int mat = lane >> 3, r = lane & 7;
    uint32_t aoff = (uint32_t)(((mat & 1) * 8 + r) * ASTR + (mat >> 1) * 16);
    uint32_t boff = (uint32_t)(r * BSTR + ((lane >> 3) & 1) * 16);
    const __nv_bfloat16* Bh = g_Mbh + (size_t)NGROUP * EN * EK;
    const __nv_bfloat16* Bl = g_Mbl + (size_t)NGROUP * EN * EK;

    int row0 = blockIdx.x * 64;
    int cnt = min(64, NE - row0);

    for (int idx = tid; idx < 64 * 26; idx += 256) {
        int row = idx / 26, seg = idx - row * 26;
        uint32_t hi4[4] = {0, 0, 0, 0}, lo4[4] = {0, 0, 0, 0};
        if (seg < 25 && row < cnt) {
            const float* p = &ent_emb[(size_t)(row0 + row) * DI + seg * 8];
#pragma unroll
            for (int qd = 0; qd < 4; qd++) {
                float v0 = p[qd * 2], v1 = p[qd * 2 + 1];
                hi4[qd] = (uint32_t)bf16h(v0) | ((uint32_t)bf16h(v1) << 16);
                lo4[qd] = (uint32_t)bf16l(v0) | ((uint32_t)bf16l(v1) << 16);
            }
        }
        uint32_t so = (uint32_t)(row * ASTR + seg * 16);
        *(uint4*)(sm + A_HI + so) = make_uint4(hi4[0], hi4[1], hi4[2], hi4[3]);
        *(uint4*)(sm + A_LO + so) = make_uint4(lo4[0], lo4[1], lo4[2], lo4[3]);
    }

    float acc[2][14][4];
#pragma unroll
    for (int mt = 0; mt < 2; mt++)
#pragma unroll
        for (int nt = 0; nt < 14; nt++)
#pragma unroll
            for (int qd = 0; qd < 4; qd++) acc[mt][nt][qd] = 0.f;

    for (int kc = 0; kc < 13; kc++) {
        __syncthreads();
        for (int idx = tid; idx < EN * 2; idx += 256) {
            int o = idx >> 1, half = idx & 1;
            size_t goff = (size_t)o * EK + kc * 16 + half * 8;
            *(uint4*)(sm + B_HI + o * BSTR + half * 16) = *(const uint4*)&Bh[goff];
            *(uint4*)(sm + B_LO + o * BSTR + half * 16) = *(const uint4*)&Bl[goff];
        }
        __syncthreads();
        uint32_t ah[2][4], al[2][4];
#pragma unroll
        for (int mt = 0; mt < 2; mt++) {
            uint32_t ab = (uint32_t)((wm * 32 + mt * 16) * ASTR + kc * 32) + aoff;
            ldsm_x4(ah[mt], sbase + A_HI + ab);
            ldsm_x4(al[mt], sbase + A_LO + ab);
        }
#pragma unroll
        for (int nt = 0; nt < 14; nt++) {
            uint32_t bh2[2], bl2[2];
            uint32_t bb = (uint32_t)((wn * 112 + nt * 8) * BSTR) + boff;
            ldsm_x2(bh2, sbase + B_HI + bb);
            ldsm_x2(bl2, sbase + B_LO + bb);
#pragma unroll
            for (int mt = 0; mt < 2; mt++) {
                mma16816(acc[mt][nt], ah[mt], bh2);
                mma16816(acc[mt][nt], ah[mt], bl2);
                mma16816(acc[mt][nt], al[mt], bh2);
            }
        }
    }

#pragma unroll
    for (int mt = 0; mt < 2; mt++) {
        int er0 = wm * 32 + mt * 16 + gq;
        int er1 = er0 + 8;
#pragma unroll
        for (int qt = 0; qt < 7; qt++) {
            int c = wn * 112 + qt * 16 + tg * 4;
            if (c < DO) {
                float4 b4 = *(const float4*)&bias_w[c];
                float* a0 = acc[mt][2 * qt];
                float* a1 = acc[mt][2 * qt + 1];
                if (er0 < cnt)
                    *(float4*)&g_x[(size_t)(row0 + er0) * DO + c] =
                        make_float4(a0[0] + b4.x, a0[1] + b4.y, a1[0] + b4.z, a1[1] + b4.w);
                if (er1 < cnt)
                    *(float4*)&g_x[(size_t)(row0 + er1) * DO + c] =
                        make_float4(a0[2] + b4.x, a0[3] + b4.y, a1[2] + b4.z, a1[3] + b4.w);
            }
        }
    }
}

// ---------------- BN column stats ----------------
__global__ void k_stats() {
    int c = threadIdx.x;
    float s = 0.f, q = 0.f;
    for (int r = blockIdx.x; r < NE; r += gridDim.x) {
        float v = g_x[(size_t)r * DO + c];
        s += v;
        q += v * v;
    }
    atomicAdd(&g_stats[c], s);
    atomicAdd(&g_stats[DO + c], q);
}

__global__ void k_bn(const float* __restrict__ gamma, const float* __restrict__ beta) {
    int c = threadIdx.x;
    if (c < DO) {
        float mean = g_stats[c] / (float)NE;
        float var = g_stats[DO + c] / (float)NE - mean * mean;
        float sc = gamma[c] * rsqrtf(var + BN_EPS);
        g_scale[c] = sc;
        g_shift[c] = beta[c] - mean * sc;
    }
}

// ---------------- r = rel_emb @ w_rel ----------------
__global__ void k_rel(const float* __restrict__ rel_emb, const float* __restrict__ w_rel) {
    int idx = blockIdx.x * blockDim.x + threadIdx.x;
    if (idx < NR * DO) {
        int row = idx / DO, col = idx - row * DO;
        float acc = 0.f;
        for (int k = 0; k < DI; k++)
            acc = fmaf(rel_emb[row * DI + k], w_rel[k * DO + col], acc);
        g_r[idx] = acc;
    }
}

// ---------------- obj = tanh(bn(x[head])) * r[rel] -> bf16 hi/lo ----------------
__global__ void k_obj(const int* __restrict__ triples) {
    int i = blockIdx.x;
    int c = threadIdx.x;
    float v = 0.f;
    if (c < DO) {
        int h = triples[3 * i], rl = triples[3 * i + 1];
        float t = tanhf(g_x[(size_t)h * DO + c] * g_scale[c] + g_shift[c]);
        v = t * g_r[rl * DO + c];
    }
    __nv_bfloat16 hi = __float2bfloat16(v);
    g_obj_hi[i * KP + c] = hi;
    g_obj_lo[i * KP + c] = __float2bfloat16(v - __bfloat162float(hi));
}

// ---------------- emb -> bf16 hi/lo, padded to KP ----------------
__global__ void k_split_emb(const float* __restrict__ emb) {
    int row = blockIdx.x;
    int c = threadIdx.x;
    float v = (c < DO) ? emb[(size_t)row * DO + c] : 0.f;
    __nv_bfloat16 hi = __float2bfloat16(v);
    size_t idx = (size_t)row * KP + c;
    g_emb_hi[idx] = hi;
    g_emb_lo[idx] = __float2bfloat16(v - __bfloat162float(hi));
}

// ---------------- score via mma.sync (partial last K-chunk) ----------------
#define SSTR 144
#define PLANE (128 * SSTR)
__global__ void __launch_bounds__(256) k_score_mma(
    const float* __restrict__ ebias, float* __restrict__ out) {
    extern __shared__ char sm[];
    uint32_t sbase = smem_u32(sm);
    const uint32_t A_HI = 0, A_LO = PLANE, B_HI = 2 * PLANE, B_LO = 3 * PLANE;

    int tid = threadIdx.x, wid = tid >> 5, lane = tid & 31;
    int wm = wid >> 2, wn = wid & 3;
    int i0 = blockIdx.x * 128;
    int e0 = blockIdx.y * 128;
    int g = lane >> 2, tg = lane & 3;

    int mat = lane >> 3, r = lane & 7;
    uint32_t aoff = (uint32_t)(((mat & 1) * 8 + r) * SSTR + (mat >> 1) * 16);
    uint32_t boff = (uint32_t)(r * SSTR + ((lane >> 3) & 1) * 16);

    float acc[4][4][4] = {};

    for (int ch = 0; ch < 7; ch++) {
        int k0 = ch * 64;
        int nseg = (ch == 6) ? 2 : 8;
        int ksl = (ch == 6) ? 1 : 4;
        __syncthreads();
        const uint4 z4 = make_uint4(0, 0, 0, 0);
        for (int idx = tid; idx < 128 * nseg; idx += 256) {
            int row = idx / nseg, seg = idx - row * nseg;
            uint32_t so = (uint32_t)(row * SSTR + seg * 16);
            *(uint4*)(sm + A_HI + so) =
                *(const uint4*)&g_obj_hi[(size_t)(i0 + row) * KP + k0 + seg * 8];
            *(uint4*)(sm + A_LO + so) =
                *(const uint4*)&g_obj_lo[(size_t)(i0 + row) * KP + k0 + seg * 8];
            int e = e0 + row;
            uint4 vh = z4, vl = z4;
            if (e < NE) {
                vh = *(const uint4*)&g_emb_hi[(size_t)e * KP + k0 + seg * 8];
                vl = *(const uint4*)&g_emb_lo[(size_t)e * KP + k0 + seg * 8];
            }
            *(uint4*)(sm + B_HI + so) = vh;
            *(uint4*)(sm + B_LO + so) = vl;
        }
        __syncthreads();

        for (int ks = 0; ks < ksl; ks++) {
            uint32_t ah[4][4], al[4][4], bh[4][2], bl[4][2];
#pragma unroll
            for (int mt = 0; mt < 4; mt++) {
                uint32_t ab = (uint32_t)((wm * 64 + mt * 16) * SSTR + ks * 32) + aoff;
                ldsm_x4(ah[mt], sbase + A_HI + ab);
                ldsm_x4(al[mt], sbase + A_LO + ab);
            }
#pragma unroll
            for (int nt = 0; nt < 4; nt++) {
                uint32_t bb = (uint32_t)((wn * 32 + nt * 8) * SSTR + ks * 32) + boff;
                ldsm_x2(bh[nt], sbase + B_HI + bb);
                ldsm_x2(bl[nt], sbase + B_LO + bb);
            }
#pragma unroll
            for (int mt = 0; mt < 4; mt++)
#pragma unroll
                for (int nt = 0; nt < 4; nt++) {
                    mma16816(acc[mt][nt], ah[mt], bh[nt]);
                    mma16816(acc[mt][nt], ah[mt], bl[nt]);
                    mma16816(acc[mt][nt], al[mt], bh[nt]);
                }
        }
    }

#pragma unroll
    for (int mt = 0; mt < 4; mt++) {
        int row = i0 + wm * 64 + mt * 16 + g;
#pragma unroll
        for (int nt = 0; nt < 4; nt++) {
            int col = e0 + wn * 32 + nt * 8 + tg * 2;
            if (col < NE) {
                float b0 = ebias[col], b1 = ebias[col + 1];
                float2 v0;
                v0.x = 1.f / (1.f + __expf(-(acc[mt][nt][0] + b0)));
                v0.y = 1.f / (1.f + __expf(-(acc[mt][nt][1] + b1)));
                *(float2*)&out[(size_t)row * NE + col] = v0;
                float2 v1;
                v1.x = 1.f / (1.f + __expf(-(acc[mt][nt][2] + b0)));
                v1.y = 1.f / (1.f + __expf(-(acc[mt][nt][3] + b1)));
                *(float2*)&out[(size_t)(row + 8) * NE + col] = v1;
            }
        }
    }
}

// ---------------- launch ----------------
extern "C" void kernel_launch(void* const* d_in, const int* in_sizes, int n_in,
                              void* d_out, int out_size) {
    const float* ent_emb  = (const float*)d_in[0];
    const float* rel_emb  = (const float*)d_in[1];
    const float* in_w     = (const float*)d_in[2];
    const float* out_w    = (const float*)d_in[3];
    const float* loop_w   = (const float*)d_in[4];
    const float* w_rel    = (const float*)d_in[5];
    const float* loop_rel = (const float*)d_in[6];
    const float* bias_w   = (const float*)d_in[7];
    const float* bn_gamma = (const float*)d_in[8];
    const float* bn_beta  = (const float*)d_in[9];
    const float* emb_ent  = (const float*)d_in[10];
    const float* ent_bias = (const float*)d_in[11];
    const int*   src      = (const int*)d_in[12];
    const int*   dst      = (const int*)d_in[13];
    const int*   et       = (const int*)d_in[14];
    const float* enorm    = (const float*)d_in[15];
    const int*   triples  = (const int*)d_in[16];
    float* out = (float*)d_out;

    cudaFuncSetAttribute(k_edge_mma, cudaFuncAttributeMaxDynamicSharedMemorySize, EDGE_SMEM2);
    cudaFuncSetAttribute(k_loopx_mma, cudaFuncAttributeMaxDynamicSharedMemorySize, LOOP_SMEM);
    const int SM_SCORE = 4 * PLANE;
    cudaFuncSetAttribute(k_score_mma, cudaFuncAttributeMaxDynamicSharedMemorySize, SM_SCORE);

    k_zero<<<4, 256>>>();
    k_hist<<<HB, 1024>>>(et);
    k_scan<<<1, 1024>>>();
    k_scatter<<<HB, 1024>>>(et);
    k_splitW<<<dim3(448, 3), 256>>>(in_w, out_w, loop_w);
    k_M_mma<<<dim3(7, 801), 256>>>(rel_emb, loop_rel);
    k_split_emb<<<NE, KP>>>(emb_ent);
    k_loopx_mma<<<(NE + 63) / 64, 256, LOOP_SMEM>>>(ent_emb, bias_w);
    k_edge_mma<<<dim3(1, 4 * NGROUP), ETH, EDGE_SMEM2>>>(ent_emb, src, dst, enorm);
    k_stats<<<512, 400>>>();
    k_bn<<<1, 512>>>(bn_gamma, bn_beta);
    k_rel<<<(NR * DO + 255) / 256, 256>>>(rel_emb, w_rel);
    k_obj<<<NB, KP>>>(triples);
    k_score_mma<<<dim3(NB / 128, (NE + 127) / 128), 256, SM_SCORE>>>(ent_bias, out);
}

// round 17
// speedup vs baseline: 1.5250x; 1.5250x over previous
#include <cuda_runtime.h>
#include <cuda_bf16.h>
#include <cstdint>
#include <math.h>

#define NE 100000
#define NR 400
#define DI 200
#define DO 400
#define NEDGE 600000
#define HALFE 300000
#define NB 1024
#define NGROUP 800
#define BN_EPS 1e-5f

#define KP 448
#define EN 448
#define EK 208

typedef unsigned long long u64;

// ---------------- device scratch ----------------
__device__ __nv_bfloat16 g_Mbh[(size_t)(NGROUP + 1) * EN * EK];
__device__ __nv_bfloat16 g_Mbl[(size_t)(NGROUP + 1) * EN * EK];
__device__ __nv_bfloat16 g_Wth[(size_t)3 * 448 * EK];
__device__ __nv_bfloat16 g_Wtl[(size_t)3 * 448 * EK];
__device__ float g_x[(size_t)NE * DO];
__device__ float g_stats[2 * DO];
__device__ float g_scale[DO];
__device__ float g_shift[DO];
__device__ float g_r[NR * DO];
__device__ __nv_bfloat16 g_obj_hi[NB * KP];
__device__ __nv_bfloat16 g_obj_lo[NB * KP];
__device__ __nv_bfloat16 g_emb_hi[(size_t)NE * KP];
__device__ __nv_bfloat16 g_emb_lo[(size_t)NE * KP];
__device__ int   g_hist[NGROUP];
__device__ int   g_off[NGROUP + 1];
__device__ int   g_pos[NGROUP];
__device__ int   g_eidx[NEDGE];

// ---------------- helpers ----------------
__device__ __forceinline__ void red4(float* p, float a, float b, float c, float d) {
    asm volatile("red.global.add.v4.f32 [%0], {%1,%2,%3,%4};"
                 :: "l"(p), "f"(a), "f"(b), "f"(c), "f"(d) : "memory");
}
__device__ __forceinline__ uint32_t smem_u32(const void* p) {
    uint32_t a;
    asm("{ .reg .u64 t; cvta.to.shared.u64 t, %1; cvt.u32.u64 %0, t; }" : "=r"(a) : "l"(p));
    return a;
}
__device__ __forceinline__ void ldsm_x4(uint32_t* r, uint32_t a) {
    asm volatile("ldmatrix.sync.aligned.m8n8.x4.shared.b16 {%0,%1,%2,%3}, [%4];"
                 : "=r"(r[0]), "=r"(r[1]), "=r"(r[2]), "=r"(r[3]) : "r"(a));
}
__device__ __forceinline__ void ldsm_x2(uint32_t* r, uint32_t a) {
    asm volatile("ldmatrix.sync.aligned.m8n8.x2.shared.b16 {%0,%1}, [%2];"
                 : "=r"(r[0]), "=r"(r[1]) : "r"(a));
}
__device__ __forceinline__ void mma16816(float* d, const uint32_t* a, const uint32_t* b) {
    asm volatile(
        "mma.sync.aligned.m16n8k16.row.col.f32.bf16.bf16.f32 "
        "{%0,%1,%2,%3}, {%4,%5,%6,%7}, {%8,%9}, {%0,%1,%2,%3};"
        : "+f"(d[0]), "+f"(d[1]), "+f"(d[2]), "+f"(d[3])
        : "r"(a[0]), "r"(a[1]), "r"(a[2]), "r"(a[3]), "r"(b[0]), "r"(b[1]));
}
__device__ __forceinline__ ushort bf16h(float v) {
    return __bfloat16_as_ushort(__float2bfloat16(v));
}
__device__ __forceinline__ ushort bf16l(float v) {
    __nv_bfloat16 h = __float2bfloat16(v);
    return __bfloat16_as_ushort(__float2bfloat16(v - __bfloat162float(h)));
}

// ---------------- zero small scratch ----------------
__global__ void k_zero() {
    int gid = blockIdx.x * blockDim.x + threadIdx.x;
    if (gid < NGROUP) g_hist[gid] = 0;
    if (gid < 2 * DO) g_stats[gid] = 0.f;
}

// ---------------- edge grouping: smem-aggregated hist ----------------
#define HB 148
__global__ void __launch_bounds__(1024) k_hist(const int* __restrict__ et) {
    __shared__ int sh[NGROUP];
    for (int i = threadIdx.x; i < NGROUP; i += 1024) sh[i] = 0;
    __syncthreads();
    int chunk = (NEDGE + HB - 1) / HB;
    int e0 = blockIdx.x * chunk;
    int e1 = min(e0 + chunk, NEDGE);
    for (int e = e0 + threadIdx.x; e < e1; e += 1024)
        atomicAdd(&sh[et[e] + (e < HALFE ? 0 : 400)], 1);
    __syncthreads();
    for (int i = threadIdx.x; i < NGROUP; i += 1024)
        if (sh[i]) atomicAdd(&g_hist[i], sh[i]);
}

__global__ void k_scan() {
    __shared__ int s[NGROUP];
    int i = threadIdx.x;
    if (i < NGROUP) s[i] = g_hist[i];
    __syncthreads();
    for (int d = 1; d < NGROUP; d <<= 1) {
        int v = 0;
        if (i < NGROUP && i >= d) v = s[i - d];
        __syncthreads();
        if (i < NGROUP && i >= d) s[i] += v;
        __syncthreads();
    }
    if (i < NGROUP) {
        int excl = s[i] - g_hist[i];
        g_off[i] = excl;
        g_pos[i] = excl;
        if (i == NGROUP - 1) g_off[NGROUP] = s[i];
    }
}

// ---------------- smem-aggregated scatter ----------------
__global__ void __launch_bounds__(1024) k_scatter(const int* __restrict__ et) {
    __shared__ int cnt[NGROUP];
    __shared__ int wr[NGROUP];
    for (int i = threadIdx.x; i < NGROUP; i += 1024) cnt[i] = 0;
    __syncthreads();
    int chunk = (NEDGE + HB - 1) / HB;
    int e0 = blockIdx.x * chunk;
    int e1 = min(e0 + chunk, NEDGE);
    for (int e = e0 + threadIdx.x; e < e1; e += 1024)
        atomicAdd(&cnt[et[e] + (e < HALFE ? 0 : 400)], 1);
    __syncthreads();
    for (int i = threadIdx.x; i < NGROUP; i += 1024)
        wr[i] = cnt[i] ? atomicAdd(&g_pos[i], cnt[i]) : 0;
    __syncthreads();
    for (int e = e0 + threadIdx.x; e < e1; e += 1024) {
        int g = et[e] + (e < HALFE ? 0 : 400);
        int p = atomicAdd(&wr[g], 1);
        g_eidx[p] = e;
    }
}

// ---------------- W^T bf16 split (once) ----------------
__global__ void k_splitW(const float* __restrict__ in_w, const float* __restrict__ out_w,
                         const float* __restrict__ loop_w) {
    int widx = blockIdx.y, o = blockIdx.x;
    const float* W = widx == 0 ? in_w : (widx == 1 ? out_w : loop_w);
    for (int j = threadIdx.x; j < EK; j += 256) {
        float v = (j < DI && o < DO) ? W[(size_t)j * DO + o] : 0.f;
        size_t off = ((size_t)widx * 448 + o) * EK + j;
        g_Wth[off] = __float2bfloat16(v);
        __nv_bfloat16 h = __float2bfloat16(v);
        g_Wtl[off] = __float2bfloat16(v - __bfloat162float(h));
    }
}

// ---------------- M^T = W^T @ C_b^T via mma.sync ----------------
#define MB 48
__global__ void __launch_bounds__(256) k_M_mma(
    const float* __restrict__ rel_emb, const float* __restrict__ loop_rel) {
    __shared__ ushort s_b[4][472];
    __shared__ char sA[2][64 * MB];
    __shared__ char sB[2][208 * MB];

    int m = blockIdx.y, strip = blockIdx.x;
    int widx = m < 400 ? 0 : (m < 800 ? 1 : 2);
    const float* bsrc = (m < 800) ? rel_emb + (size_t)(m % 400) * DI : loop_rel;
    int tid = threadIdx.x;

    for (int s = tid; s < 464; s += 256) {
        float v0 = bsrc[s % DI];
        float v1 = bsrc[(s + 1) % DI];
        s_b[0][s] = bf16h(v0);
        s_b[2][s] = bf16l(v0);
        s_b[1][s] = bf16h(v1);
        s_b[3][s] = bf16l(v1);
    }

    int wid = tid >> 5, lane = tid & 31;
    int wm = wid >> 1, wn = wid & 1;
    int gq = lane >> 2, tg = lane & 3;
    int mat = lane >> 3, r = lane & 7;
    uint32_t aoff = (uint32_t)(((mat & 1) * 8 + r) * MB + (mat >> 1) * 16);
    uint32_t boff = (uint32_t)(r * MB + ((lane >> 3) & 1) * 16);
    uint32_t baseA0 = smem_u32(sA[0]), baseA1 = smem_u32(sA[1]);
    uint32_t baseB0 = smem_u32(sB[0]), baseB1 = smem_u32(sB[1]);

    float acc[13][4] = {};

    for (int kc = 0; kc < 13; kc++) {
        __syncthreads();
        {
            int idx = tid;
            int p = idx >> 7, rem = idx & 127;
            int row = rem >> 1, half = rem & 1;
            const __nv_bfloat16* gW = p ? g_Wtl : g_Wth;
            size_t goff = ((size_t)widx * 448 + strip * 64 + row) * EK + kc * 16 + half * 8;
            *(uint4*)(sA[p] + row * MB + half * 16) = *(const uint4*)&gW[goff];
        }
        for (int idx = tid; idx < 416; idx += 256) {
            int p = (idx >= 208) ? 1 : 0;
            int t = idx - p * 208;
            int bi = t + kc * 16;
            int par = bi & 1;
            const uint32_t* sp = (const uint32_t*)&s_b[p * 2 + par][bi - par];
            uint32_t w0 = sp[0], w1 = sp[1], w2 = sp[2], w3 = sp[3];
            uint32_t w4 = sp[4], w5 = sp[5], w6 = sp[6], w7 = sp[7];
            *(uint4*)(sB[p] + t * MB) = make_uint4(w0, w1, w2, w3);
            *(uint4*)(sB[p] + t * MB + 16) = make_uint4(w4, w5, w6, w7);
        }
        __syncthreads();
        uint32_t ah[4], al[4];
        uint32_t ab = (uint32_t)((wm * 16) * MB) + aoff;
        ldsm_x4(ah, baseA0 + ab);
        ldsm_x4(al, baseA1 + ab);
#pragma unroll
        for (int nt = 0; nt < 13; nt++) {
            uint32_t bh2[2], bl2[2];
            uint32_t bb = (uint32_t)((wn * 104 + nt * 8) * MB) + boff;
            ldsm_x2(bh2, baseB0 + bb);
            ldsm_x2(bl2, baseB1 + bb);
            mma16816(acc[nt], ah, bh2);
            mma16816(acc[nt], ah, bl2);
            mma16816(acc[nt], al, bh2);
        }
    }

    const float S = 1.f / 3.f;
    int o0 = strip * 64 + wm * 16;
#pragma unroll
    for (int nt = 0; nt < 13; nt++) {
        int t = wn * 104 + nt * 8 + tg * 2;
#pragma unroll
        for (int rr = 0; rr < 2; rr++) {
            int o = o0 + gq + rr * 8;
            int ml = o & 15;
            int pm = ((ml & 2) << 2) | ((ml & 12) >> 1) | (ml & 1);
            int operm = (o & ~15) | pm;
            float v0 = acc[nt][rr * 2 + 0] * S, v1 = acc[nt][rr * 2 + 1] * S;
            uint32_t hp = (uint32_t)bf16h(v0) | ((uint32_t)bf16h(v1) << 16);
            uint32_t lp = (uint32_t)bf16l(v0) | ((uint32_t)bf16l(v1) << 16);
            size_t off = ((size_t)m * EN + operm) * EK + t;
            *(uint32_t*)&g_Mbh[off] = hp;
            *(uint32_t*)&g_Mbl[off] = lp;
        }
    }
}

// ---------------- edge messages: resident-B quarters, 512 threads, static acc ----------------
#define ET2 128
#define XSTR 432
#define EA_BYTES (ET2 * XSTR)
#define EB_BYTES (112 * XSTR)
#define EDGE_SMEM2 (2 * EA_BYTES + 2 * EB_BYTES)
#define ETH 512

template <int NTQ>
__device__ __forceinline__ void edge_body(
    int g, int q, const float* __restrict__ ent_emb, const int* __restrict__ src,
    const int* __restrict__ dst, const float* __restrict__ nrm,
    int* s_src, int* s_dst, float* s_nrm) {
    extern __shared__ char sm[];
    uint32_t sbase = smem_u32(sm);
    const uint32_t A_HI = 0, A_LO = EA_BYTES, B_HI = 2 * EA_BYTES,
                   B_LO = 2 * EA_BYTES + EB_BYTES;

    int base = g_off[g];
    int ng = g_off[g + 1] - base;
    if (ng == 0) return;
    const int ROWS = NTQ * 8;
    const int NPAIR = NTQ / 2;
    const int PH = (NPAIR + 1) / 2;        // compile-time max pairs per warp-half
    int tid = threadIdx.x, wid = tid >> 5, lane = tid & 31;
    int wm = wid & 7, wh = wid >> 3;       // row-tile, n-half
    int pbase = wh * PH;                   // first pair for this half
    int myPairs = wh ? (NPAIR - PH) : PH;  // runtime, warp-uniform
    int gq = lane >> 2, tg = lane & 3;
    int mat = lane >> 3, r = lane & 7;
    uint32_t aoff = (uint32_t)(((mat & 1) * 8 + r) * XSTR + (mat >> 1) * 16);
    uint32_t boff = (uint32_t)(r * XSTR + ((lane >> 3) & 1) * 16);
    const __nv_bfloat16* Bh = g_Mbh + ((size_t)g * EN + q * 112) * EK;
    const __nv_bfloat16* Bl = g_Mbl + ((size_t)g * EN + q * 112) * EK;

    for (int idx = tid; idx < ROWS * 26 * 2; idx += ETH) {
        int p = (idx >= ROWS * 26) ? 1 : 0;
        int rem = idx - p * ROWS * 26;
        int row = rem / 26, seg = rem - row * 26;
        const __nv_bfloat16* gB = p ? Bl : Bh;
        uint32_t d = (p ? B_LO : B_HI) + row * XSTR + seg * 16;
        *(uint4*)(sm + d) = *(const uint4*)&gB[(size_t)row * EK + seg * 8];
    }

    for (int t0 = 0; t0 < ng; t0 += ET2) {
        int cnt = min(ET2, ng - t0);
        __syncthreads();
        if (tid < ET2) {
            if (tid < cnt) {
                int e = g_eidx[base + t0 + tid];
                s_src[tid] = src[e];
                s_dst[tid] = dst[e];
                s_nrm[tid] = nrm[e];
            } else {
                s_src[tid] = 0;
                s_dst[tid] = 0;
                s_nrm[tid] = 0.f;
            }
        }
        __syncthreads();
        for (int idx = tid; idx < ET2 * 26; idx += ETH) {
            int row = idx / 26, seg = idx - row * 26;
            uint32_t hi4[4] = {0, 0, 0, 0}, lo4[4] = {0, 0, 0, 0};
            if (seg < 25) {
                const float* p = &ent_emb[(size_t)s_src[row] * DI + seg * 8];
                float nv = s_nrm[row];
#pragma unroll
                for (int qd = 0; qd < 4; qd++) {
                    float v0 = p[qd * 2] * nv, v1 = p[qd * 2 + 1] * nv;
                    hi4[qd] = (uint32_t)bf16h(v0) | ((uint32_t)bf16h(v1) << 16);
                    lo4[qd] = (uint32_t)bf16l(v0) | ((uint32_t)bf16l(v1) << 16);
                }
            }
            uint32_t so = (uint32_t)(row * XSTR + seg * 16);
            *(uint4*)(sm + A_HI + so) = make_uint4(hi4[0], hi4[1], hi4[2], hi4[3]);
            *(uint4*)(sm + A_LO + so) = make_uint4(lo4[0], lo4[1], lo4[2], lo4[3]);
        }
        __syncthreads();

        float acc[2 * PH][4];   // statically indexed -> registers
#pragma unroll
        for (int nt = 0; nt < 2 * PH; nt++)
#pragma unroll
            for (int qd = 0; qd < 4; qd++) acc[nt][qd] = 0.f;

        for (int kc = 0; kc < 13; kc++) {
            uint32_t ah[4], al[4];
            uint32_t ab = (uint32_t)((wm * 16) * XSTR + kc * 32) + aoff;
            ldsm_x4(ah, sbase + A_HI + ab);
            ldsm_x4(al, sbase + A_LO + ab);
#pragma unroll
            for (int pt = 0; pt < PH; pt++) {
                if (pt < myPairs) {
#pragma unroll
                    for (int half = 0; half < 2; half++) {
                        int ntl = 2 * (pbase + pt) + half;
                        uint32_t bh2[2], bl2[2];
                        uint32_t bb = (uint32_t)((ntl * 8) * XSTR + kc * 32) + boff;
                        ldsm_x2(bh2, sbase + B_HI + bb);
                        ldsm_x2(bl2, sbase + B_LO + bb);
                        float* a = acc[2 * pt + half];
                        mma16816(a, ah, bh2);
                        mma16816(a, ah, bl2);
                        mma16816(a, al, bh2);
                    }
                }
            }
        }

        int er0 = wm * 16 + gq;
        int er1 = er0 + 8;
#pragma unroll
        for (int pt = 0; pt < PH; pt++) {
            if (pt < myPairs) {
                int c = q * 112 + (pbase + pt) * 16 + tg * 4;
                float* a0 = acc[2 * pt];
                float* a1 = acc[2 * pt + 1];
                if (er0 < cnt)
                    red4(&g_x[(size_t)s_dst[er0] * DO + c], a0[0], a0[1], a1[0], a1[1]);
                if (er1 < cnt)
                    red4(&g_x[(size_t)s_dst[er1] * DO + c], a0[2], a0[3], a1[2], a1[3]);
            }
        }
    }
}

__global__ void __launch_bounds__(ETH) k_edge_mma(
    const float* __restrict__ ent_emb, const int* __restrict__ src,
    const int* __restrict__ dst, const float* __restrict__ nrm) {
    __shared__ int s_src[ET2];
    __shared__ int s_dst[ET2];
    __shared__ float s_nrm[ET2];
    int gq4 = blockIdx.y;
    int g = gq4 >> 2, q = gq4 & 3;
    if (q == 3)
        edge_body<8>(g, q, ent_emb, src, dst, nrm, s_src, s_dst, s_nrm);
    else
        edge_body<14>(g, q, ent_emb, src, dst, nrm, s_src, s_dst, s_nrm);
}

// ---------------- self-loop (runs FIRST): x = loop + bias ----------------
#define ASTR 432
#define BSTR 48
#define LA_BYTES (64 * ASTR)
#define LB_BYTES (EN * BSTR)
#define LOOP_SMEM (2 * LA_BYTES + 2 * LB_BYTES)

__global__ void __launch_bounds__(256) k_loopx_mma(
    const float* __restrict__ ent_emb, const float* __restrict__ bias_w) {
    extern __shared__ char sm[];
    uint32_t sbase = smem_u32(sm);
    const uint32_t A_HI = 0, A_LO = LA_BYTES, B_HI = 2 * LA_BYTES, B_LO = 2 * LA_BYTES + LB_BYTES;

    int tid = threadIdx.x, wid = tid >> 5, lane = tid & 31;
    int wm = wid >> 2, wn = wid & 3;
    int gq = lane >> 2, tg = lane & 3;
    int mat = lane >> 3, r = lane & 7;
    uint32_t aoff = (uint32_t)(((mat & 1) * 8 + r) * ASTR + (mat >> 1) * 16);
    uint32_t boff = (uint32_t)(r * BSTR + ((lane >> 3) & 1) * 16);
    const __nv_bfloat16* Bh = g_Mbh + (size_t)NGROUP * EN * EK;
    const __nv_bfloat16* Bl = g_Mbl + (size_t)NGROUP * EN * EK;

    int row0 = blockIdx.x * 64;
    int cnt = min(64, NE - row0);

    for (int idx = tid; idx < 64 * 26; idx += 256) {
        int row = idx / 26, seg = idx - row * 26;
        uint32_t hi4[4] = {0, 0, 0, 0}, lo4[4] = {0, 0, 0, 0};
        if (seg < 25 && row < cnt) {
            const float* p = &ent_emb[(size_t)(row0 + row) * DI + seg * 8];
#pragma unroll
            for (int qd = 0; qd < 4; qd++) {
                float v0 = p[qd * 2], v1 = p[qd * 2 + 1];
                hi4[qd] = (uint32_t)bf16h(v0) | ((uint32_t)bf16h(v1) << 16);
                lo4[qd] = (uint32_t)bf16l(v0) | ((uint32_t)bf16l(v1) << 16);
            }
        }
        uint32_t so = (uint32_t)(row * ASTR + seg * 16);
        *(uint4*)(sm + A_HI + so) = make_uint4(hi4[0], hi4[1], hi4[2], hi4[3]);
        *(uint4*)(sm + A_LO + so) = make_uint4(lo4[0], lo4[1], lo4[2], lo4[3]);
    }

    float acc[2][14][4];
#pragma unroll
    for (int mt = 0; mt < 2; mt++)
#pragma unroll
        for (int nt = 0; nt < 14; nt++)
#pragma unroll
            for (int qd = 0; qd < 4; qd++) acc[mt][nt][qd] = 0.f;

    for (int kc = 0; kc < 13; kc++) {
        __syncthreads();
        for (int idx = tid; idx < EN * 2; idx += 256) {
            int o = idx >> 1, half = idx & 1;
            size_t goff = (size_t)o * EK + kc * 16 + half * 8;
            *(uint4*)(sm + B_HI + o * BSTR + half * 16) = *(const uint4*)&Bh[goff];
            *(uint4*)(sm + B_LO + o * BSTR + half * 16) = *(const uint4*)&Bl[goff];
        }
        __syncthreads();
        uint32_t ah[2][4], al[2][4];
#pragma unroll
        for (int mt = 0; mt < 2; mt++) {
            uint32_t ab = (uint32_t)((wm * 32 + mt * 16) * ASTR + kc * 32) + aoff;
            ldsm_x4(ah[mt], sbase + A_HI + ab);
            ldsm_x4(al[mt], sbase + A_LO + ab);
        }
#pragma unroll
        for (int nt = 0; nt < 14; nt++) {
            uint32_t bh2[2], bl2[2];
            uint32_t bb = (uint32_t)((wn * 112 + nt * 8) * BSTR) + boff;
            ldsm_x2(bh2, sbase + B_HI + bb);
            ldsm_x2(bl2, sbase + B_LO + bb);
#pragma unroll
            for (int mt = 0; mt < 2; mt++) {
                mma16816(acc[mt][nt], ah[mt], bh2);
                mma16816(acc[mt][nt], ah[mt], bl2);
                mma16816(acc[mt][nt], al[mt], bh2);
            }
        }
    }

#pragma unroll
    for (int mt = 0; mt < 2; mt++) {
        int er0 = wm * 32 + mt * 16 + gq;
        int er1 = er0 + 8;
#pragma unroll
        for (int qt = 0; qt < 7; qt++) {
            int c = wn * 112 + qt * 16 + tg * 4;
            if (c < DO) {
                float4 b4 = *(const float4*)&bias_w[c];
                float* a0 = acc[mt][2 * qt];
                float* a1 = acc[mt][2 * qt + 1];
                if (er0 < cnt)
                    *(float4*)&g_x[(size_t)(row0 + er0) * DO + c] =
                        make_float4(a0[0] + b4.x, a0[1] + b4.y, a1[0] + b4.z, a1[1] + b4.w);
                if (er1 < cnt)
                    *(float4*)&g_x[(size_t)(row0 + er1) * DO + c] =
                        make_float4(a0[2] + b4.x, a0[3] + b4.y, a1[2] + b4.z, a1[3] + b4.w);
            }
        }
    }
}

// ---------------- BN column stats ----------------
__global__ void k_stats() {
    int c = threadIdx.x;
    float s = 0.f, q = 0.f;
    for (int r = blockIdx.x; r < NE; r += gridDim.x) {
        float v = g_x[(size_t)r * DO + c];
        s += v;
        q += v * v;
    }
    atomicAdd(&g_stats[c], s);
    atomicAdd(&g_stats[DO + c], q);
}

__global__ void k_bn(const float* __restrict__ gamma, const float* __restrict__ beta) {
    int c = threadIdx.x;
    if (c < DO) {
        float mean = g_stats[c] / (float)NE;
        float var = g_stats[DO + c] / (float)NE - mean * mean;
        float sc = gamma[c] * rsqrtf(var + BN_EPS);
        g_scale[c] = sc;
        g_shift[c] = beta[c] - mean * sc;
    }
}

// ---------------- r = rel_emb @ w_rel ----------------
__global__ void k_rel(const float* __restrict__ rel_emb, const float* __restrict__ w_rel) {
    int idx = blockIdx.x * blockDim.x + threadIdx.x;
    if (idx < NR * DO) {
        int row = idx / DO, col = idx - row * DO;
        float acc = 0.f;
        for (int k = 0; k < DI; k++)
            acc = fmaf(rel_emb[row * DI + k], w_rel[k * DO + col], acc);
        g_r[idx] = acc;
    }
}

// ---------------- obj = tanh(bn(x[head])) * r[rel] -> bf16 hi/lo ----------------
__global__ void k_obj(const int* __restrict__ triples) {
    int i = blockIdx.x;
    int c = threadIdx.x;
    float v = 0.f;
    if (c < DO) {
        int h = triples[3 * i], rl = triples[3 * i + 1];
        float t = tanhf(g_x[(size_t)h * DO + c] * g_scale[c] + g_shift[c]);
        v = t * g_r[rl * DO + c];
    }
    __nv_bfloat16 hi = __float2bfloat16(v);
    g_obj_hi[i * KP + c] = hi;
    g_obj_lo[i * KP + c] = __float2bfloat16(v - __bfloat162float(hi));
}

// ---------------- emb -> bf16 hi/lo, padded to KP ----------------
__global__ void k_split_emb(const float* __restrict__ emb) {
    int row = blockIdx.x;
    int c = threadIdx.x;
    float v = (c < DO) ? emb[(size_t)row * DO + c] : 0.f;
    __nv_bfloat16 hi = __float2bfloat16(v);
    size_t idx = (size_t)row * KP + c;
    g_emb_hi[idx] = hi;
    g_emb_lo[idx] = __float2bfloat16(v - __bfloat162float(hi));
}

// ---------------- score via mma.sync (partial last K-chunk) ----------------
#define SSTR 144
#define PLANE (128 * SSTR)
__global__ void __launch_bounds__(256) k_score_mma(
    const float* __restrict__ ebias, float* __restrict__ out) {
    extern __shared__ char sm[];
    uint32_t sbase = smem_u32(sm);
    const uint32_t A_HI = 0, A_LO = PLANE, B_HI = 2 * PLANE, B_LO = 3 * PLANE;

    int tid = threadIdx.x, wid = tid >> 5, lane = tid & 31;
    int wm = wid >> 2, wn = wid & 3;
    int i0 = blockIdx.x * 128;
    int e0 = blockIdx.y * 128;
    int g = lane >> 2, tg = lane & 3;

    int mat = lane >> 3, r = lane & 7;
    uint32_t aoff = (uint32_t)(((mat & 1) * 8 + r) * SSTR + (mat >> 1) * 16);
    uint32_t boff = (uint32_t)(r * SSTR + ((lane >> 3) & 1) * 16);

    float acc[4][4][4] = {};

    for (int ch = 0; ch < 7; ch++) {
        int k0 = ch * 64;
        int nseg = (ch == 6) ? 2 : 8;
        int ksl = (ch == 6) ? 1 : 4;
        __syncthreads();
        const uint4 z4 = make_uint4(0, 0, 0, 0);
        for (int idx = tid; idx < 128 * nseg; idx += 256) {
            int row = idx / nseg, seg = idx - row * nseg;
            uint32_t so = (uint32_t)(row * SSTR + seg * 16);
            *(uint4*)(sm + A_HI + so) =
                *(const uint4*)&g_obj_hi[(size_t)(i0 + row) * KP + k0 + seg * 8];
            *(uint4*)(sm + A_LO + so) =
                *(const uint4*)&g_obj_lo[(size_t)(i0 + row) * KP + k0 + seg * 8];
            int e = e0 + row;
            uint4 vh = z4, vl = z4;
            if (e < NE) {
                vh = *(const uint4*)&g_emb_hi[(size_t)e * KP + k0 + seg * 8];
                vl = *(const uint4*)&g_emb_lo[(size_t)e * KP + k0 + seg * 8];
            }
            *(uint4*)(sm + B_HI + so) = vh;
            *(uint4*)(sm + B_LO + so) = vl;
        }
        __syncthreads();

        for (int ks = 0; ks < ksl; ks++) {
            uint32_t ah[4][4], al[4][4], bh[4][2], bl[4][2];
#pragma unroll
            for (int mt = 0; mt < 4; mt++) {
                uint32_t ab = (uint32_t)((wm * 64 + mt * 16) * SSTR + ks * 32) + aoff;
                ldsm_x4(ah[mt], sbase + A_HI + ab);
                ldsm_x4(al[mt], sbase + A_LO + ab);
            }
#pragma unroll
            for (int nt = 0; nt < 4; nt++) {
                uint32_t bb = (uint32_t)((wn * 32 + nt * 8) * SSTR + ks * 32) + boff;
                ldsm_x2(bh[nt], sbase + B_HI + bb);
                ldsm_x2(bl[nt], sbase + B_LO + bb);
            }
#pragma unroll
            for (int mt = 0; mt < 4; mt++)
#pragma unroll
                for (int nt = 0; nt < 4; nt++) {
                    mma16816(acc[mt][nt], ah[mt], bh[nt]);
                    mma16816(acc[mt][nt], ah[mt], bl[nt]);
                    mma16816(acc[mt][nt], al[mt], bh[nt]);
                }
        }
    }

#pragma unroll
    for (int mt = 0; mt < 4; mt++) {
        int row = i0 + wm * 64 + mt * 16 + g;
#pragma unroll
        for (int nt = 0; nt < 4; nt++) {
            int col = e0 + wn * 32 + nt * 8 + tg * 2;
            if (col < NE) {
                float b0 = ebias[col], b1 = ebias[col + 1];
                float2 v0;
                v0.x = 1.f / (1.f + __expf(-(acc[mt][nt][0] + b0)));
                v0.y = 1.f / (1.f + __expf(-(acc[mt][nt][1] + b1)));
                *(float2*)&out[(size_t)row * NE + col] = v0;
                float2 v1;
                v1.x = 1.f / (1.f + __expf(-(acc[mt][nt][2] + b0)));
                v1.y = 1.f / (1.f + __expf(-(acc[mt][nt][3] + b1)));
                *(float2*)&out[(size_t)(row + 8) * NE + col] = v1;
            }
        }
    }
}

// ---------------- launch ----------------
extern "C" void kernel_launch(void* const* d_in, const int* in_sizes, int n_in,
                              void* d_out, int out_size) {
    const float* ent_emb  = (const float*)d_in[0];
    const float* rel_emb  = (const float*)d_in[1];
    const float* in_w     = (const float*)d_in[2];
    const float* out_w    = (const float*)d_in[3];
    const float* loop_w   = (const float*)d_in[4];
    const float* w_rel    = (const float*)d_in[5];
    const float* loop_rel = (const float*)d_in[6];
    const float* bias_w   = (const float*)d_in[7];
    const float* bn_gamma = (const float*)d_in[8];
    const float* bn_beta  = (const float*)d_in[9];
    const float* emb_ent  = (const float*)d_in[10];
    const float* ent_bias = (const float*)d_in[11];
    const int*   src      = (const int*)d_in[12];
    const int*   dst      = (const int*)d_in[13];
    const int*   et       = (const int*)d_in[14];
    const float* enorm    = (const float*)d_in[15];
    const int*   triples  = (const int*)d_in[16];
    float* out = (float*)d_out;

    cudaFuncSetAttribute(k_edge_mma, cudaFuncAttributeMaxDynamicSharedMemorySize, EDGE_SMEM2);
    cudaFuncSetAttribute(k_loopx_mma, cudaFuncAttributeMaxDynamicSharedMemorySize, LOOP_SMEM);
    const int SM_SCORE = 4 * PLANE;
    cudaFuncSetAttribute(k_score_mma, cudaFuncAttributeMaxDynamicSharedMemorySize, SM_SCORE);

    k_zero<<<4, 256>>>();
    k_hist<<<HB, 1024>>>(et);
    k_scan<<<1, 1024>>>();
    k_scatter<<<HB, 1024>>>(et);
    k_splitW<<<dim3(448, 3), 256>>>(in_w, out_w, loop_w);
    k_M_mma<<<dim3(7, 801), 256>>>(rel_emb, loop_rel);
    k_split_emb<<<NE, KP>>>(emb_ent);
    k_loopx_mma<<<(NE + 63) / 64, 256, LOOP_SMEM>>>(ent_emb, bias_w);
    k_edge_mma<<<dim3(1, 4 * NGROUP), ETH, EDGE_SMEM2>>>(ent_emb, src, dst, enorm);
    k_stats<<<512, 400>>>();
    k_bn<<<1, 512>>>(bn_gamma, bn_beta);
    k_rel<<<(NR * DO + 255) / 256, 256>>>(rel_emb, w_rel);
    k_obj<<<NB, KP>>>(triples);
    k_score_mma<<<dim3(NB / 128, (NE + 127) / 128), 256, SM_SCORE>>>(ent_bias, out);
}